// round 2
// baseline (speedup 1.0000x reference)
#include <cuda_runtime.h>

#define NDIM 65
#define ND2  4225
#define NV   274625
#define NVB  1073                       /* 256-vertex blocks                */
#define NT   1572864                    /* 64^3 * 6 tets                    */
#define TPT  8                          /* tets per thread in ktA           */
#define TILE_T (256*TPT)                /* 2048 tets per tile               */
#define NTT  (NT/TILE_T)                /* 768 tiles                        */

// -------- scratch (device globals; no allocations allowed) --------
__device__ unsigned char      g_mask[NV];
__device__ int                g_vloc[NV];
__device__ int                g_vblk[NVB];
__device__ unsigned int       g_tloc[NT];    // lo16 = c1 local, hi16 = c2 local
__device__ unsigned long long g_tblk[NTT];   // lo32 = c1 base,  hi32 = c2 base
__device__ int                g_M;
__device__ int                g_F1;

__constant__ signed char c_tri[16][6] = {
  {-1,-1,-1,-1,-1,-1},{1,0,2,-1,-1,-1},{4,0,3,-1,-1,-1},{1,4,2,1,3,4},
  {3,1,5,-1,-1,-1},{2,3,0,2,5,3},{1,4,0,1,5,4},{4,2,5,-1,-1,-1},
  {4,5,2,-1,-1,-1},{4,1,0,4,5,1},{3,2,0,3,5,2},{1,3,5,-1,-1,-1},
  {4,1,2,4,3,1},{3,0,4,-1,-1,-1},{2,0,1,-1,-1,-1},{-1,-1,-1,-1,-1,-1}};
__constant__ signed char c_ntri[16] = {0,1,1,2,1,2,2,1,1,2,2,1,2,1,1,0};
__constant__ signed char c_ea[6] = {0,0,0,1,1,2};
__constant__ signed char c_eb[6] = {1,2,3,2,3,3};
__constant__ signed char c_kuhn[6][4] = {
  {0,1,3,7},{0,3,2,7},{0,2,6,7},{0,6,4,7},{0,4,5,7},{0,5,1,7}};

// corner bit b -> vid offset ; bit0 -> i, bit1 -> j, bit2 -> k
__device__ __forceinline__ int corner_off(int b) {
    return (b & 1) * ND2 + ((b >> 1) & 1) * NDIM + ((b >> 2) & 1);
}

// ---------------- warp-shuffle block scan (256 threads) ----------------
template <typename T>
__device__ __forceinline__ T blockScanExcl256(T val, T& total) {
    unsigned lane = threadIdx.x & 31, w = threadIdx.x >> 5;
    T incl = val;
    #pragma unroll
    for (int o = 1; o < 32; o <<= 1) {
        T n = __shfl_up_sync(0xffffffffu, incl, o);
        if (lane >= o) incl += n;
    }
    __shared__ T ws[8];
    if (lane == 31) ws[w] = incl;
    __syncthreads();
    if (w == 0) {
        T x = (lane < 8) ? ws[lane] : T(0);
        #pragma unroll
        for (int o = 1; o < 8; o <<= 1) {
            T n = __shfl_up_sync(0xffffffffu, x, o);
            if (lane >= o) x += n;
        }
        if (lane < 8) ws[lane] = x;
    }
    __syncthreads();
    T base = (w > 0) ? ws[w - 1] : T(0);
    total = ws[7];
    return base + incl - val;
}

// ---------------- kA: vertex crossing masks + block scan ----------------
__global__ void kA(const float* __restrict__ level, const int* __restrict__ thrp) {
    int v = blockIdx.x * 256 + threadIdx.x;
    unsigned int mask = 0;
    float thr = (float)thrp[0];
    if (v < NV) {
        int i = v / ND2;
        int r = v - i * ND2;
        int j = r / NDIM;
        int k = r - j * NDIM;
        bool o0 = (level[v] - thr) > 0.0f;
        #pragma unroll
        for (int d = 1; d < 8; ++d) {
            int di = d >> 2, dj = (d >> 1) & 1, dk = d & 1;
            if (i + di < NDIM && j + dj < NDIM && k + dk < NDIM) {
                bool o1 = (level[v + di * ND2 + dj * NDIM + dk] - thr) > 0.0f;
                if (o0 != o1) mask |= 1u << (d - 1);
            }
        }
    }
    int cnt = __popc(mask);
    int total;
    int excl = blockScanExcl256<int>(cnt, total);
    if (v < NV) {
        g_mask[v] = (unsigned char)mask;
        g_vloc[v] = excl;
    }
    if (threadIdx.x == 0) g_vblk[blockIdx.x] = total;
}

// ---------------- scanV: 1073 ints, single block 1024 threads ----------------
__global__ void kScanV() {
    int t = threadIdx.x;
    int i0 = 2 * t, i1 = 2 * t + 1;
    int e0 = (i0 < NVB) ? g_vblk[i0] : 0;
    int e1 = (i1 < NVB) ? g_vblk[i1] : 0;
    int val = e0 + e1;
    unsigned lane = t & 31, w = t >> 5;
    int incl = val;
    #pragma unroll
    for (int o = 1; o < 32; o <<= 1) {
        int n = __shfl_up_sync(0xffffffffu, incl, o);
        if (lane >= o) incl += n;
    }
    __shared__ int ws[32];
    if (lane == 31) ws[w] = incl;
    __syncthreads();
    if (w == 0) {
        int x = ws[lane];
        #pragma unroll
        for (int o = 1; o < 32; o <<= 1) {
            int n = __shfl_up_sync(0xffffffffu, x, o);
            if (lane >= o) x += n;
        }
        ws[lane] = x;
    }
    __syncthreads();
    int excl = ((w > 0) ? ws[w - 1] : 0) + incl - val;
    if (i0 < NVB) g_vblk[i0] = excl;
    if (i1 < NVB) g_vblk[i1] = excl + e0;
    if (t == 1023) g_M = excl + val;
}

// ---------------- ktA: tet classification (analytic) + tile scan ----------------
__global__ void ktA(const float* __restrict__ level, const int* __restrict__ thrp) {
    int t0 = (blockIdx.x * 256 + threadIdx.x) * TPT;
    float thr = (float)thrp[0];
    unsigned int codes[TPT];
    unsigned int sum = 0;
    #pragma unroll
    for (int l = 0; l < TPT; ++l) {
        int t = t0 + l;
        unsigned cube = (unsigned)t / 6u;
        int ku = t - (int)cube * 6;
        int ci = cube >> 12, cj = (cube >> 6) & 63, ck = cube & 63;
        int v000 = (ci * NDIM + cj) * NDIM + ck;
        int ti = 0;
        #pragma unroll
        for (int p = 0; p < 4; ++p) {
            int b = c_kuhn[ku][p];
            if ((level[v000 + corner_off(b)] - thr) > 0.0f) ti |= 1 << p;
        }
        int nt = c_ntri[ti];
        unsigned int c = (nt == 1) ? 1u : ((nt == 2) ? 0x10000u : 0u);
        codes[l] = c;
        sum += c;
    }
    unsigned int total;
    unsigned int excl = blockScanExcl256<unsigned int>(sum, total);
    unsigned int run = excl;
    #pragma unroll
    for (int l = 0; l < TPT; ++l) { g_tloc[t0 + l] = run; run += codes[l]; }
    if (threadIdx.x == 0)
        g_tblk[blockIdx.x] = (unsigned long long)(total & 0xFFFFu)
                           | ((unsigned long long)(total >> 16) << 32);
}

// ---------------- scanT: 768 u64, single block 768 threads ----------------
__global__ void kScanT() {
    int t = threadIdx.x;
    unsigned long long val = g_tblk[t];
    unsigned lane = t & 31, w = t >> 5;
    unsigned long long incl = val;
    #pragma unroll
    for (int o = 1; o < 32; o <<= 1) {
        unsigned long long n = __shfl_up_sync(0xffffffffu, incl, o);
        if (lane >= o) incl += n;
    }
    __shared__ unsigned long long ws[24];
    if (lane == 31) ws[w] = incl;
    __syncthreads();
    if (w == 0) {
        unsigned long long x = (lane < 24) ? ws[lane] : 0ull;
        #pragma unroll
        for (int o = 1; o < 32; o <<= 1) {
            unsigned long long n = __shfl_up_sync(0xffffffffu, x, o);
            if (lane >= o) x += n;
        }
        if (lane < 24) ws[lane] = x;
    }
    __syncthreads();
    unsigned long long excl = ((w > 0) ? ws[w - 1] : 0ull) + incl - val;
    g_tblk[t] = excl;
    if (t == 767) g_F1 = (int)((excl + val) & 0xFFFFFFFFull);
}

// ---------------- kB: emit interpolated vertices (analytic pos) ----------------
__global__ void kB(const float* __restrict__ level, const int* __restrict__ thrp,
                   float* __restrict__ out) {
    int v = blockIdx.x * 256 + threadIdx.x;
    if (v >= NV) return;
    unsigned int mask = g_mask[v];
    if (!mask) return;
    float thr = (float)thrp[0];
    const float inv = 1.0f / 64.0f;
    int i = v / ND2;
    int r = v - i * ND2;
    int j = r / NDIM;
    int k = r - j * NDIM;
    int idx = g_vloc[v] + g_vblk[blockIdx.x];
    float s0  = level[v] - thr;
    float p0x = (float)i * inv, p0y = (float)j * inv, p0z = (float)k * inv;
    #pragma unroll
    for (int d = 1; d < 8; ++d) {
        if (mask & (1u << (d - 1))) {
            int di = d >> 2, dj = (d >> 1) & 1, dk = d & 1;
            int w = v + di * ND2 + dj * NDIM + dk;
            float s1 = level[w] - thr;
            float denom = s0 - s1;
            float w0 = (-s1) / denom;
            float w1 = s0 / denom;
            out[3 * idx + 0] = p0x * w0 + (float)(i + di) * inv * w1;
            out[3 * idx + 1] = p0y * w0 + (float)(j + dj) * inv * w1;
            out[3 * idx + 2] = p0z * w0 + (float)(k + dk) * inv * w1;
            idx++;
        }
    }
}

// ---------------- ktB: emit faces (analytic tets) ----------------
__global__ void ktB(const float* __restrict__ level, const int* __restrict__ thrp,
                    float* __restrict__ out) {
    int t = blockIdx.x * 256 + threadIdx.x;
    float thr = (float)thrp[0];
    unsigned cube = (unsigned)t / 6u;
    int ku = t - (int)cube * 6;
    int ci = cube >> 12, cj = (cube >> 6) & 63, ck = cube & 63;
    int v000 = (ci * NDIM + cj) * NDIM + ck;
    int ti = 0;
    #pragma unroll
    for (int p = 0; p < 4; ++p) {
        int b = c_kuhn[ku][p];
        if ((level[v000 + corner_off(b)] - thr) > 0.0f) ti |= 1 << p;
    }
    int nt = c_ntri[ti];
    if (nt == 0) return;

    unsigned int       loc = g_tloc[t];
    unsigned long long blk = g_tblk[t >> 11];
    int fbase;
    if (nt == 1)
        fbase = (int)(loc & 0xFFFFu) + (int)(blk & 0xFFFFFFFFull);
    else
        fbase = g_F1 + 2 * ((int)(loc >> 16) + (int)(blk >> 32));

    float* fout = out + 3ll * g_M;
    for (int e = 0; e < 3 * nt; ++e) {
        int le = c_tri[ti][e];
        int ba = c_kuhn[ku][(int)c_ea[le]];
        int bb = c_kuhn[ku][(int)c_eb[le]];
        int lo = ba & bb;          // subset corner = smaller vid
        int dd = ba ^ bb;          // direction bits (i,j,k)
        int vmin = v000 + corner_off(lo);
        int bit = (((dd & 1) << 2) | (dd & 2) | ((dd >> 2) & 1)) - 1;
        int vidx = g_vloc[vmin] + g_vblk[vmin >> 8]
                 + __popc((unsigned int)g_mask[vmin] & ((1u << bit) - 1u));
        fout[3 * fbase + e] = (float)vidx;
    }
}

// ---------------- launch ----------------
extern "C" void kernel_launch(void* const* d_in, const int* in_sizes, int n_in,
                              void* d_out, int out_size) {
    const float* level = (const float*)d_in[0];
    const int*   thrp  = (const int*)d_in[3];
    float*       out   = (float*)d_out;
    (void)in_sizes; (void)n_in; (void)out_size;

    kA    <<<NVB, 256>>>(level, thrp);
    kScanV<<<1, 1024>>>();
    ktA   <<<NTT, 256>>>(level, thrp);
    kScanT<<<1, 768>>>();
    kB    <<<NVB, 256>>>(level, thrp, out);
    ktB   <<<NT / 256, 256>>>(level, thrp, out);
}

// round 3
// speedup vs baseline: 2.3873x; 2.3873x over previous
#include <cuda_runtime.h>

#define NDIM 65
#define ND2  4225
#define NV   274625
#define NVB  1073            /* 256-vertex blocks            */
#define NC   262144          /* 64^3 cubes                   */
#define NCB  1024            /* cube blocks of 256           */
#define NOCW 8592            /* occupancy words (padded)     */

// -------- scratch (device globals; no allocations allowed) --------
__device__ unsigned char      g_mask[NV];    // 7-bit crossing mask per vertex
__device__ int                g_vloc[NV];    // exclusive-in-block vert prefix
__device__ int                g_vblk[NVB];   // block bases (scanned)
__device__ unsigned int       g_occw[NOCW];  // occupancy bits, 1 per vertex
__device__ unsigned long long g_tblk[NCB];   // lo32=c1 base, hi32=c2 base
__device__ int                g_M;
__device__ int                g_F1;

// runtime-indexed tables live in __device__ globals (L1 path, no LDC serialization)
__device__ const signed char d_tri[96] = {
  -1,-1,-1,-1,-1,-1,  1,0,2,-1,-1,-1,  4,0,3,-1,-1,-1,  1,4,2,1,3,4,
   3,1,5,-1,-1,-1,    2,3,0,2,5,3,     1,4,0,1,5,4,     4,2,5,-1,-1,-1,
   4,5,2,-1,-1,-1,    4,1,0,4,5,1,     3,2,0,3,5,2,     1,3,5,-1,-1,-1,
   4,1,2,4,3,1,       3,0,4,-1,-1,-1,  2,0,1,-1,-1,-1, -1,-1,-1,-1,-1,-1};
__device__ const signed char d_ea[6]   = {0,0,0,1,1,2};
__device__ const signed char d_eb[6]   = {1,2,3,2,3,3};
__device__ const signed char d_kuhn[24] = {0,1,3,7, 0,3,2,7, 0,2,6,7,
                                           0,6,4,7, 0,4,5,7, 0,5,1,7};

// corner bit b (bit0->i, bit1->j, bit2->k) -> vid offset
__device__ __forceinline__ int corner_off(int b) {
    return (b & 1) * ND2 + ((b >> 1) & 1) * NDIM + ((b >> 2) & 1);
}

// extract occ bit for vertex id
__device__ __forceinline__ unsigned occ_bit(int vid) {
    return (g_occw[vid >> 5] >> (vid & 31)) & 1u;
}

// ---------------- warp-shuffle block scan (256 threads) ----------------
template <typename T>
__device__ __forceinline__ T blockScanExcl256(T val, T& total) {
    unsigned lane = threadIdx.x & 31, w = threadIdx.x >> 5;
    T incl = val;
    #pragma unroll
    for (int o = 1; o < 32; o <<= 1) {
        T n = __shfl_up_sync(0xffffffffu, incl, o);
        if (lane >= o) incl += n;
    }
    __shared__ T ws[8];
    if (lane == 31) ws[w] = incl;
    __syncthreads();
    if (w == 0) {
        T x = (lane < 8) ? ws[lane] : T(0);
        #pragma unroll
        for (int o = 1; o < 8; o <<= 1) {
            T n = __shfl_up_sync(0xffffffffu, x, o);
            if (lane >= o) x += n;
        }
        if (lane < 8) ws[lane] = x;
    }
    __syncthreads();
    T base = (w > 0) ? ws[w - 1] : T(0);
    total = ws[7];
    return base + incl - val;
}

// ---------------- kA: masks + occupancy ballot + block scan ----------------
__global__ void kA(const float* __restrict__ level, const int* __restrict__ thrp) {
    int v = blockIdx.x * 256 + threadIdx.x;
    unsigned int mask = 0;
    bool o0 = false;
    float thr = (float)thrp[0];
    if (v < NV) {
        int i = v / ND2;
        int r = v - i * ND2;
        int j = r / NDIM;
        int k = r - j * NDIM;
        o0 = (level[v] - thr) > 0.0f;
        #pragma unroll
        for (int d = 1; d < 8; ++d) {
            int di = d >> 2, dj = (d >> 1) & 1, dk = d & 1;
            if (i + di < NDIM && j + dj < NDIM && k + dk < NDIM) {
                bool o1 = (level[v + di * ND2 + dj * NDIM + dk] - thr) > 0.0f;
                if (o0 != o1) mask |= 1u << (d - 1);
            }
        }
    }
    unsigned bw = __ballot_sync(0xffffffffu, o0);
    if ((threadIdx.x & 31) == 0) g_occw[v >> 5] = bw;

    int cnt = __popc(mask);
    int total;
    int excl = blockScanExcl256<int>(cnt, total);
    if (v < NV) {
        g_mask[v] = (unsigned char)mask;
        g_vloc[v] = excl;
    }
    if (threadIdx.x == 0) g_vblk[blockIdx.x] = total;
}

// per-cube tet codes: returns packed sum (lo16=#1tri, hi16=#2tri), fills ti6[]
__device__ __forceinline__ unsigned cube_codes(unsigned occ8, int* ti6) {
    const int ka[6] = {1,3,2,6,4,5};
    const int kb[6] = {3,2,6,4,5,1};
    unsigned sum = 0;
    #pragma unroll
    for (int ku = 0; ku < 6; ++ku) {
        int ti = (int)(occ8 & 1u)
               | (int)(((occ8 >> ka[ku]) & 1u) << 1)
               | (int)(((occ8 >> kb[ku]) & 1u) << 2)
               | (int)(((occ8 >> 7) & 1u) << 3);
        ti6[ku] = ti;
        int pc = __popc(ti);
        int nt = min(pc, 4 - pc);
        sum += (nt == 1) ? 1u : ((nt == 2) ? 0x10000u : 0u);
    }
    return sum;
}

__device__ __forceinline__ unsigned load_occ8(int v000) {
    unsigned occ8 = 0;
    #pragma unroll
    for (int b = 0; b < 8; ++b)
        occ8 |= occ_bit(v000 + corner_off(b)) << b;
    return occ8;
}

// ---------------- ktA: per-block tet class reduce ----------------
__global__ void ktA() {
    int cube = blockIdx.x * 256 + threadIdx.x;
    int ci = cube >> 12, cj = (cube >> 6) & 63, ck = cube & 63;
    int v000 = (ci * NDIM + cj) * NDIM + ck;
    int ti6[6];
    unsigned sum = cube_codes(load_occ8(v000), ti6);

    // block reduce (packed u32; c1 max 1536, c2 max 1536 — no overflow)
    #pragma unroll
    for (int o = 16; o > 0; o >>= 1) sum += __shfl_down_sync(0xffffffffu, sum, o);
    __shared__ unsigned ws[8];
    unsigned lane = threadIdx.x & 31, w = threadIdx.x >> 5;
    if (lane == 0) ws[w] = sum;
    __syncthreads();
    if (threadIdx.x == 0) {
        unsigned tot = 0;
        #pragma unroll
        for (int x = 0; x < 8; ++x) tot += ws[x];
        g_tblk[blockIdx.x] = (unsigned long long)(tot & 0xFFFFu)
                           | ((unsigned long long)(tot >> 16) << 32);
    }
}

// ---------------- kScan: both small scans in one launch ----------------
__global__ void kScan() {
    int t = threadIdx.x;
    unsigned lane = t & 31, w = t >> 5;

    // ---- part 1: vertex block bases (1073 ints, 2/thread) ----
    {
        int i0 = 2 * t, i1 = 2 * t + 1;
        int e0 = (i0 < NVB) ? g_vblk[i0] : 0;
        int e1 = (i1 < NVB) ? g_vblk[i1] : 0;
        int val = e0 + e1;
        int incl = val;
        #pragma unroll
        for (int o = 1; o < 32; o <<= 1) {
            int n = __shfl_up_sync(0xffffffffu, incl, o);
            if (lane >= o) incl += n;
        }
        __shared__ int wsA[32];
        if (lane == 31) wsA[w] = incl;
        __syncthreads();
        if (w == 0) {
            int x = wsA[lane];
            #pragma unroll
            for (int o = 1; o < 32; o <<= 1) {
                int n = __shfl_up_sync(0xffffffffu, x, o);
                if (lane >= o) x += n;
            }
            wsA[lane] = x;
        }
        __syncthreads();
        int excl = ((w > 0) ? wsA[w - 1] : 0) + incl - val;
        if (i0 < NVB) g_vblk[i0] = excl;
        if (i1 < NVB) g_vblk[i1] = excl + e0;
        if (t == 1023) g_M = excl + val;
        __syncthreads();
    }

    // ---- part 2: tet block bases (1024 u64) ----
    {
        unsigned long long val = g_tblk[t];
        unsigned long long incl = val;
        #pragma unroll
        for (int o = 1; o < 32; o <<= 1) {
            unsigned long long n = __shfl_up_sync(0xffffffffu, incl, o);
            if (lane >= o) incl += n;
        }
        __shared__ unsigned long long wsB[32];
        if (lane == 31) wsB[w] = incl;
        __syncthreads();
        if (w == 0) {
            unsigned long long x = wsB[lane];
            #pragma unroll
            for (int o = 1; o < 32; o <<= 1) {
                unsigned long long n = __shfl_up_sync(0xffffffffu, x, o);
                if (lane >= o) x += n;
            }
            wsB[lane] = x;
        }
        __syncthreads();
        unsigned long long excl = ((w > 0) ? wsB[w - 1] : 0ull) + incl - val;
        g_tblk[t] = excl;
        if (t == 1023) g_F1 = (int)((excl + val) & 0xFFFFFFFFull);
    }
}

// ---------------- kB: emit interpolated vertices (analytic pos) ----------------
__global__ void kB(const float* __restrict__ level, const int* __restrict__ thrp,
                   float* __restrict__ out) {
    int v = blockIdx.x * 256 + threadIdx.x;
    if (v >= NV) return;
    unsigned int mask = g_mask[v];
    if (!mask) return;
    float thr = (float)thrp[0];
    const float inv = 1.0f / 64.0f;
    int i = v / ND2;
    int r = v - i * ND2;
    int j = r / NDIM;
    int k = r - j * NDIM;
    int idx = g_vloc[v] + g_vblk[blockIdx.x];
    float s0  = level[v] - thr;
    float p0x = (float)i * inv, p0y = (float)j * inv, p0z = (float)k * inv;
    #pragma unroll
    for (int d = 1; d < 8; ++d) {
        if (mask & (1u << (d - 1))) {
            int di = d >> 2, dj = (d >> 1) & 1, dk = d & 1;
            int w = v + di * ND2 + dj * NDIM + dk;
            float s1 = level[w] - thr;
            float denom = s0 - s1;
            float w0 = (-s1) / denom;
            float w1 = s0 / denom;
            out[3 * idx + 0] = p0x * w0 + (float)(i + di) * inv * w1;
            out[3 * idx + 1] = p0y * w0 + (float)(j + dj) * inv * w1;
            out[3 * idx + 2] = p0z * w0 + (float)(k + dk) * inv * w1;
            idx++;
        }
    }
}

// ---------------- ktB: emit faces (cube-based, shared tables) ----------------
__global__ void ktB(float* __restrict__ out) {
    __shared__ int s_tri[96];
    __shared__ int s_edge[36];
    int tid = threadIdx.x;
    if (tid < 96) s_tri[tid] = d_tri[tid];
    if (tid < 36) {
        int ku = tid / 6, le = tid - ku * 6;
        int ba = d_kuhn[ku * 4 + d_ea[le]];
        int bb = d_kuhn[ku * 4 + d_eb[le]];
        int lo = ba & bb;
        int dd = ba ^ bb;
        int off = corner_off(lo);
        int bit = (((dd & 1) << 2) | (dd & 2) | ((dd >> 2) & 1)) - 1;
        s_edge[tid] = (off << 3) | bit;
    }

    int cube = blockIdx.x * 256 + tid;
    int ci = cube >> 12, cj = (cube >> 6) & 63, ck = cube & 63;
    int v000 = (ci * NDIM + cj) * NDIM + ck;
    int ti6[6];
    unsigned sum = cube_codes(load_occ8(v000), ti6);

    unsigned total;
    unsigned run = blockScanExcl256<unsigned>(sum, total);  // syncs cover table writes

    unsigned long long blk = g_tblk[blockIdx.x];
    int c1base = (int)(blk & 0xFFFFFFFFull);
    int c2base = (int)(blk >> 32);
    int F1 = g_F1;
    float* fout = out + 3ll * g_M;

    #pragma unroll
    for (int ku = 0; ku < 6; ++ku) {
        int ti = ti6[ku];
        int pc = __popc(ti);
        int nt = min(pc, 4 - pc);
        if (nt == 0) continue;
        int fbase;
        unsigned code;
        if (nt == 1) {
            fbase = (int)(run & 0xFFFFu) + c1base;
            code = 1u;
        } else {
            fbase = F1 + 2 * ((int)(run >> 16) + c2base);
            code = 0x10000u;
        }
        int nent = 3 * nt;
        for (int e = 0; e < nent; ++e) {
            int le = s_tri[ti * 6 + e];
            int pe = s_edge[ku * 6 + le];
            int vmin = v000 + (pe >> 3);
            unsigned bit = (unsigned)(pe & 7);
            int vidx = g_vloc[vmin] + g_vblk[vmin >> 8]
                     + __popc((unsigned)g_mask[vmin] & ((1u << bit) - 1u));
            fout[3 * fbase + e] = (float)vidx;
        }
        run += code;
    }
}

// ---------------- launch ----------------
extern "C" void kernel_launch(void* const* d_in, const int* in_sizes, int n_in,
                              void* d_out, int out_size) {
    const float* level = (const float*)d_in[0];
    const int*   thrp  = (const int*)d_in[3];
    float*       out   = (float*)d_out;
    (void)in_sizes; (void)n_in; (void)out_size;

    kA    <<<NVB, 256>>>(level, thrp);
    ktA   <<<NCB, 256>>>();
    kScan <<<1, 1024>>>();
    kB    <<<NVB, 256>>>(level, thrp, out);
    ktB   <<<NCB, 256>>>(out);
}

// round 4
// speedup vs baseline: 2.8598x; 1.1979x over previous
#include <cuda_runtime.h>

#define NDIM 65
#define ND2  4225
#define NV   274625
#define NVB  1073            /* 256-vertex blocks            */
#define NC   262144          /* 64^3 cubes                   */
#define NCB  1024            /* cube blocks of 256           */
#define NOCW 8592            /* occupancy words (padded)     */

// -------- scratch (device globals; no allocations allowed) --------
__device__ unsigned char      g_mask[NV];    // 7-bit crossing mask per vertex
__device__ unsigned int       g_packed[NV];  // (global vert base << 7) | mask
__device__ int                g_vblk[NVB];   // block totals -> scanned bases
__device__ unsigned int       g_occw[NOCW];  // occupancy bits, 1 per vertex
__device__ unsigned long long g_tblk[NCB];   // lo32=c1 base, hi32=c2 base
__device__ int                g_M;
__device__ int                g_F1;

__device__ const signed char d_tri[96] = {
  -1,-1,-1,-1,-1,-1,  1,0,2,-1,-1,-1,  4,0,3,-1,-1,-1,  1,4,2,1,3,4,
   3,1,5,-1,-1,-1,    2,3,0,2,5,3,     1,4,0,1,5,4,     4,2,5,-1,-1,-1,
   4,5,2,-1,-1,-1,    4,1,0,4,5,1,     3,2,0,3,5,2,     1,3,5,-1,-1,-1,
   4,1,2,4,3,1,       3,0,4,-1,-1,-1,  2,0,1,-1,-1,-1, -1,-1,-1,-1,-1,-1};
__device__ const signed char d_ea[6]   = {0,0,0,1,1,2};
__device__ const signed char d_eb[6]   = {1,2,3,2,3,3};
__device__ const signed char d_kuhn[24] = {0,1,3,7, 0,3,2,7, 0,2,6,7,
                                           0,6,4,7, 0,4,5,7, 0,5,1,7};

// corner bit b (bit0->i, bit1->j, bit2->k) -> vid offset
__device__ __forceinline__ int corner_off(int b) {
    return (b & 1) * ND2 + ((b >> 1) & 1) * NDIM + ((b >> 2) & 1);
}

__device__ __forceinline__ unsigned occ_bit(int vid) {
    return (g_occw[vid >> 5] >> (vid & 31)) & 1u;
}

// ---------------- warp-shuffle block scan (256 threads) ----------------
template <typename T>
__device__ __forceinline__ T blockScanExcl256(T val, T& total) {
    unsigned lane = threadIdx.x & 31, w = threadIdx.x >> 5;
    T incl = val;
    #pragma unroll
    for (int o = 1; o < 32; o <<= 1) {
        T n = __shfl_up_sync(0xffffffffu, incl, o);
        if (lane >= o) incl += n;
    }
    __shared__ T ws[8];
    if (lane == 31) ws[w] = incl;
    __syncthreads();
    if (w == 0) {
        T x = (lane < 8) ? ws[lane] : T(0);
        #pragma unroll
        for (int o = 1; o < 8; o <<= 1) {
            T n = __shfl_up_sync(0xffffffffu, x, o);
            if (lane >= o) x += n;
        }
        if (lane < 8) ws[lane] = x;
    }
    __syncthreads();
    T base = (w > 0) ? ws[w - 1] : T(0);
    total = ws[7];
    return base + incl - val;
}

// ---------------- kA: masks + occupancy ballot + block reduce ----------------
__global__ void kA(const float* __restrict__ level, const int* __restrict__ thrp) {
    int v = blockIdx.x * 256 + threadIdx.x;
    unsigned int mask = 0;
    bool o0 = false;
    float thr = (float)thrp[0];
    if (v < NV) {
        int i = v / ND2;
        int r = v - i * ND2;
        int j = r / NDIM;
        int k = r - j * NDIM;
        o0 = (level[v] - thr) > 0.0f;
        #pragma unroll
        for (int d = 1; d < 8; ++d) {
            int di = d >> 2, dj = (d >> 1) & 1, dk = d & 1;
            if (i + di < NDIM && j + dj < NDIM && k + dk < NDIM) {
                bool o1 = (level[v + di * ND2 + dj * NDIM + dk] - thr) > 0.0f;
                if (o0 != o1) mask |= 1u << (d - 1);
            }
        }
    }
    unsigned bw = __ballot_sync(0xffffffffu, o0);
    if ((threadIdx.x & 31) == 0) g_occw[v >> 5] = bw;
    if (v < NV) g_mask[v] = (unsigned char)mask;

    int cnt = __popc(mask);
    #pragma unroll
    for (int o = 16; o > 0; o >>= 1) cnt += __shfl_down_sync(0xffffffffu, cnt, o);
    __shared__ int ws[8];
    unsigned lane = threadIdx.x & 31, w = threadIdx.x >> 5;
    if (lane == 0) ws[w] = cnt;
    __syncthreads();
    if (threadIdx.x == 0) {
        int tot = 0;
        #pragma unroll
        for (int x = 0; x < 8; ++x) tot += ws[x];
        g_vblk[blockIdx.x] = tot;
    }
}

// per-cube tet codes: packed sum (lo16=#1tri, hi16=#2tri), fills ti6[]
__device__ __forceinline__ unsigned cube_codes(unsigned occ8, int* ti6) {
    const int ka[6] = {1,3,2,6,4,5};
    const int kb[6] = {3,2,6,4,5,1};
    unsigned sum = 0;
    #pragma unroll
    for (int ku = 0; ku < 6; ++ku) {
        int ti = (int)(occ8 & 1u)
               | (int)(((occ8 >> ka[ku]) & 1u) << 1)
               | (int)(((occ8 >> kb[ku]) & 1u) << 2)
               | (int)(((occ8 >> 7) & 1u) << 3);
        ti6[ku] = ti;
        int pc = __popc(ti);
        int nt = min(pc, 4 - pc);
        sum += (nt == 1) ? 1u : ((nt == 2) ? 0x10000u : 0u);
    }
    return sum;
}

__device__ __forceinline__ unsigned load_occ8(int v000) {
    unsigned occ8 = 0;
    #pragma unroll
    for (int b = 0; b < 8; ++b)
        occ8 |= occ_bit(v000 + corner_off(b)) << b;
    return occ8;
}

// ---------------- ktA: per-block tet class reduce ----------------
__global__ void ktA() {
    int cube = blockIdx.x * 256 + threadIdx.x;
    int ci = cube >> 12, cj = (cube >> 6) & 63, ck = cube & 63;
    int v000 = (ci * NDIM + cj) * NDIM + ck;
    int ti6[6];
    unsigned sum = cube_codes(load_occ8(v000), ti6);

    #pragma unroll
    for (int o = 16; o > 0; o >>= 1) sum += __shfl_down_sync(0xffffffffu, sum, o);
    __shared__ unsigned ws[8];
    unsigned lane = threadIdx.x & 31, w = threadIdx.x >> 5;
    if (lane == 0) ws[w] = sum;
    __syncthreads();
    if (threadIdx.x == 0) {
        unsigned tot = 0;
        #pragma unroll
        for (int x = 0; x < 8; ++x) tot += ws[x];
        g_tblk[blockIdx.x] = (unsigned long long)(tot & 0xFFFFu)
                           | ((unsigned long long)(tot >> 16) << 32);
    }
}

// ---------------- kScan: both small scans in one launch ----------------
__global__ void kScan() {
    int t = threadIdx.x;
    unsigned lane = t & 31, w = t >> 5;

    { // vertex block bases (1073 ints, 2/thread)
        int i0 = 2 * t, i1 = 2 * t + 1;
        int e0 = (i0 < NVB) ? g_vblk[i0] : 0;
        int e1 = (i1 < NVB) ? g_vblk[i1] : 0;
        int val = e0 + e1;
        int incl = val;
        #pragma unroll
        for (int o = 1; o < 32; o <<= 1) {
            int n = __shfl_up_sync(0xffffffffu, incl, o);
            if (lane >= o) incl += n;
        }
        __shared__ int wsA[32];
        if (lane == 31) wsA[w] = incl;
        __syncthreads();
        if (w == 0) {
            int x = wsA[lane];
            #pragma unroll
            for (int o = 1; o < 32; o <<= 1) {
                int n = __shfl_up_sync(0xffffffffu, x, o);
                if (lane >= o) x += n;
            }
            wsA[lane] = x;
        }
        __syncthreads();
        int excl = ((w > 0) ? wsA[w - 1] : 0) + incl - val;
        if (i0 < NVB) g_vblk[i0] = excl;
        if (i1 < NVB) g_vblk[i1] = excl + e0;
        if (t == 1023) g_M = excl + val;
        __syncthreads();
    }

    { // tet block bases (1024 u64)
        unsigned long long val = g_tblk[t];
        unsigned long long incl = val;
        #pragma unroll
        for (int o = 1; o < 32; o <<= 1) {
            unsigned long long n = __shfl_up_sync(0xffffffffu, incl, o);
            if (lane >= o) incl += n;
        }
        __shared__ unsigned long long wsB[32];
        if (lane == 31) wsB[w] = incl;
        __syncthreads();
        if (w == 0) {
            unsigned long long x = wsB[lane];
            #pragma unroll
            for (int o = 1; o < 32; o <<= 1) {
                unsigned long long n = __shfl_up_sync(0xffffffffu, x, o);
                if (lane >= o) x += n;
            }
            wsB[lane] = x;
        }
        __syncthreads();
        unsigned long long excl = ((w > 0) ? wsB[w - 1] : 0ull) + incl - val;
        g_tblk[t] = excl;
        if (t == 1023) g_F1 = (int)((excl + val) & 0xFFFFFFFFull);
    }
}

// ---------------- kB: verts via smem staging + packed emit ----------------
__global__ void kB(const float* __restrict__ level, const int* __restrict__ thrp,
                   float* __restrict__ out) {
    __shared__ float sv[256 * 7 * 3];   // 21504 B worst case
    int v = blockIdx.x * 256 + threadIdx.x;
    unsigned int mask = 0;
    if (v < NV) mask = g_mask[v];
    int cnt = __popc(mask);
    int total;
    int excl = blockScanExcl256<int>(cnt, total);
    int gbase = g_vblk[blockIdx.x];

    if (mask) {
        float thr = (float)thrp[0];
        const float inv = 1.0f / 64.0f;
        int i = v / ND2;
        int r = v - i * ND2;
        int j = r / NDIM;
        int k = r - j * NDIM;
        g_packed[v] = ((unsigned)(gbase + excl) << 7) | mask;
        float s0  = level[v] - thr;
        float p0x = (float)i * inv, p0y = (float)j * inv, p0z = (float)k * inv;
        int sp = excl * 3;
        #pragma unroll
        for (int d = 1; d < 8; ++d) {
            if (mask & (1u << (d - 1))) {
                int di = d >> 2, dj = (d >> 1) & 1, dk = d & 1;
                int w = v + di * ND2 + dj * NDIM + dk;
                float s1 = level[w] - thr;
                float denom = s0 - s1;
                float w0 = (-s1) / denom;
                float w1 = s0 / denom;
                sv[sp + 0] = p0x * w0 + (float)(i + di) * inv * w1;
                sv[sp + 1] = p0y * w0 + (float)(j + dj) * inv * w1;
                sv[sp + 2] = p0z * w0 + (float)(k + dk) * inv * w1;
                sp += 3;
            }
        }
    }
    __syncthreads();
    float* dst = out + 3ll * gbase;
    int n = 3 * total;
    for (int x = threadIdx.x; x < n; x += 256) dst[x] = sv[x];
}

// ---------------- ktB: faces with register/smem corner cache ----------------
__global__ void ktB(float* __restrict__ out) {
    __shared__ int s_tri[96];
    __shared__ int s_edge[36];
    __shared__ unsigned s_pack[8 * 256];   // [corner][tid], conflict-free
    int tid = threadIdx.x;
    if (tid < 96) s_tri[tid] = d_tri[tid];
    if (tid < 36) {
        int ku = tid / 6, le = tid - ku * 6;
        int ba = d_kuhn[ku * 4 + d_ea[le]];
        int bb = d_kuhn[ku * 4 + d_eb[le]];
        int lo = ba & bb;
        int dd = ba ^ bb;
        int bit = (((dd & 1) << 2) | (dd & 2) | ((dd >> 2) & 1)) - 1;
        s_edge[tid] = (lo << 3) | bit;
    }

    int cube = blockIdx.x * 256 + tid;
    int ci = cube >> 12, cj = (cube >> 6) & 63, ck = cube & 63;
    int v000 = (ci * NDIM + cj) * NDIM + ck;
    int ti6[6];
    unsigned sum = cube_codes(load_occ8(v000), ti6);

    // cache the 8 corner packed words (only needed if any face exists,
    // but load unconditionally — coalesced, L1-hot)
    #pragma unroll
    for (int c = 0; c < 8; ++c)
        s_pack[c * 256 + tid] = g_packed[v000 + corner_off(c)];

    unsigned total;
    unsigned run = blockScanExcl256<unsigned>(sum, total);  // syncs cover s_* writes

    unsigned long long blk = g_tblk[blockIdx.x];
    int c1base = (int)(blk & 0xFFFFFFFFull);
    int c2base = (int)(blk >> 32);
    int F1 = g_F1;
    float* fout = out + 3ll * g_M;

    #pragma unroll
    for (int ku = 0; ku < 6; ++ku) {
        int ti = ti6[ku];
        int pc = __popc(ti);
        int nt = min(pc, 4 - pc);
        if (nt == 0) continue;
        int fbase;
        unsigned code;
        if (nt == 1) {
            fbase = (int)(run & 0xFFFFu) + c1base;
            code = 1u;
        } else {
            fbase = F1 + 2 * ((int)(run >> 16) + c2base);
            code = 0x10000u;
        }
        int nent = 3 * nt;
        for (int e = 0; e < nent; ++e) {
            int le = s_tri[ti * 6 + e];
            int pe = s_edge[ku * 6 + le];
            unsigned pk = s_pack[(pe >> 3) * 256 + tid];
            unsigned bit = (unsigned)(pe & 7);
            int vidx = (int)(pk >> 7) + __popc(pk & 0x7Fu & ((1u << bit) - 1u));
            fout[3 * fbase + e] = (float)vidx;
        }
        run += code;
    }
}

// ---------------- launch ----------------
extern "C" void kernel_launch(void* const* d_in, const int* in_sizes, int n_in,
                              void* d_out, int out_size) {
    const float* level = (const float*)d_in[0];
    const int*   thrp  = (const int*)d_in[3];
    float*       out   = (float*)d_out;
    (void)in_sizes; (void)n_in; (void)out_size;

    kA    <<<NVB, 256>>>(level, thrp);
    ktA   <<<NCB, 256>>>();
    kScan <<<1, 1024>>>();
    kB    <<<NVB, 256>>>(level, thrp, out);
    ktB   <<<NCB, 256>>>(out);
}

// round 5
// speedup vs baseline: 3.9704x; 1.3884x over previous
#include <cuda_runtime.h>

#define NDIM 65
#define ND2  4225
#define NV   274625
#define NVB  1073            /* 256-vertex blocks            */
#define NC   262144          /* 64^3 cubes                   */
#define NCB  1024            /* cube blocks of 256           */
#define NOCW 8592            /* occupancy words (padded)     */

// -------- scratch (device globals; no allocations allowed) --------
__device__ unsigned int      g_pkl[NV];      // (block-local excl << 7) | mask
__device__ int               g_vblk[NVB+1];  // block totals -> scanned bases (+ M)
__device__ unsigned int      g_occw[NOCW];   // occupancy bits
__device__ unsigned long long g_tblk[NCB];   // lo32=c1 base, hi32=c2 base
__device__ int               g_M;
__device__ int               g_F1;

__device__ const signed char d_tri[96] = {
  -1,-1,-1,-1,-1,-1,  1,0,2,-1,-1,-1,  4,0,3,-1,-1,-1,  1,4,2,1,3,4,
   3,1,5,-1,-1,-1,    2,3,0,2,5,3,     1,4,0,1,5,4,     4,2,5,-1,-1,-1,
   4,5,2,-1,-1,-1,    4,1,0,4,5,1,     3,2,0,3,5,2,     1,3,5,-1,-1,-1,
   4,1,2,4,3,1,       3,0,4,-1,-1,-1,  2,0,1,-1,-1,-1, -1,-1,-1,-1,-1,-1};
__device__ const signed char d_ea[6]   = {0,0,0,1,1,2};
__device__ const signed char d_eb[6]   = {1,2,3,2,3,3};
__device__ const signed char d_kuhn[24] = {0,1,3,7, 0,3,2,7, 0,2,6,7,
                                           0,6,4,7, 0,4,5,7, 0,5,1,7};

__device__ __forceinline__ int corner_off(int b) {
    return (b & 1) * ND2 + ((b >> 1) & 1) * NDIM + ((b >> 2) & 1);
}
__device__ __forceinline__ unsigned occ_bit(int vid) {
    return (g_occw[vid >> 5] >> (vid & 31)) & 1u;
}

// ---------------- warp-shuffle block scan (256 threads) ----------------
template <typename T>
__device__ __forceinline__ T blockScanExcl256(T val, T& total) {
    unsigned lane = threadIdx.x & 31, w = threadIdx.x >> 5;
    T incl = val;
    #pragma unroll
    for (int o = 1; o < 32; o <<= 1) {
        T n = __shfl_up_sync(0xffffffffu, incl, o);
        if (lane >= o) incl += n;
    }
    __shared__ T ws[8];
    if (lane == 31) ws[w] = incl;
    __syncthreads();
    if (w == 0) {
        T x = (lane < 8) ? ws[lane] : T(0);
        #pragma unroll
        for (int o = 1; o < 8; o <<= 1) {
            T n = __shfl_up_sync(0xffffffffu, x, o);
            if (lane >= o) x += n;
        }
        if (lane < 8) ws[lane] = x;
    }
    __syncthreads();
    T base = (w > 0) ? ws[w - 1] : T(0);
    total = ws[7];
    return base + incl - val;
}

// per-cube tet codes from occ byte: packed (lo16=#1tri, hi16=#2tri), fills ti6[]
__device__ __forceinline__ unsigned cube_codes(unsigned occ8, int* ti6) {
    const int ka[6] = {1,3,2,6,4,5};
    const int kb[6] = {3,2,6,4,5,1};
    unsigned sum = 0;
    #pragma unroll
    for (int ku = 0; ku < 6; ++ku) {
        int ti = (int)(occ8 & 1u)
               | (int)(((occ8 >> ka[ku]) & 1u) << 1)
               | (int)(((occ8 >> kb[ku]) & 1u) << 2)
               | (int)(((occ8 >> 7) & 1u) << 3);
        ti6[ku] = ti;
        int pc = __popc(ti);
        int nt = min(pc, 4 - pc);
        sum += (nt == 1) ? 1u : ((nt == 2) ? 0x10000u : 0u);
    }
    return sum;
}

// ================= kCount: fused vertex masks + tet class counts =================
__global__ void kCount(const float* __restrict__ level, const int* __restrict__ thrp) {
    float thr = (float)thrp[0];
    if (blockIdx.x < NVB) {
        // ---- vertex branch ----
        int v = blockIdx.x * 256 + threadIdx.x;
        unsigned int mask = 0;
        bool o0 = false;
        if (v < NV) {
            int i = v / ND2;
            int r = v - i * ND2;
            int j = r / NDIM;
            int k = r - j * NDIM;
            o0 = (level[v] - thr) > 0.0f;
            #pragma unroll
            for (int d = 1; d < 8; ++d) {
                int di = d >> 2, dj = (d >> 1) & 1, dk = d & 1;
                if (i + di < NDIM && j + dj < NDIM && k + dk < NDIM) {
                    bool o1 = (level[v + di * ND2 + dj * NDIM + dk] - thr) > 0.0f;
                    if (o0 != o1) mask |= 1u << (d - 1);
                }
            }
        }
        unsigned bw = __ballot_sync(0xffffffffu, o0);
        if ((threadIdx.x & 31) == 0) g_occw[v >> 5] = bw;

        int cnt = __popc(mask);
        int total;
        int excl = blockScanExcl256<int>(cnt, total);
        if (v < NV) g_pkl[v] = ((unsigned)excl << 7) | mask;
        if (threadIdx.x == 0) g_vblk[blockIdx.x] = total;
    } else {
        // ---- cube branch: classify tets straight from level ----
        int cb = blockIdx.x - NVB;
        int cube = cb * 256 + threadIdx.x;
        int ci = cube >> 12, cj = (cube >> 6) & 63, ck = cube & 63;
        int v000 = (ci * NDIM + cj) * NDIM + ck;
        unsigned occ8 = 0;
        #pragma unroll
        for (int b = 0; b < 8; ++b)
            occ8 |= ((level[v000 + corner_off(b)] - thr) > 0.0f ? 1u : 0u) << b;
        int ti6[6];
        unsigned sum = cube_codes(occ8, ti6);

        #pragma unroll
        for (int o = 16; o > 0; o >>= 1) sum += __shfl_down_sync(0xffffffffu, sum, o);
        __shared__ unsigned ws[8];
        unsigned lane = threadIdx.x & 31, w = threadIdx.x >> 5;
        if (lane == 0) ws[w] = sum;
        __syncthreads();
        if (threadIdx.x == 0) {
            unsigned tot = 0;
            #pragma unroll
            for (int x = 0; x < 8; ++x) tot += ws[x];
            g_tblk[cb] = (unsigned long long)(tot & 0xFFFFu)
                       | ((unsigned long long)(tot >> 16) << 32);
        }
    }
}

// ================= kScan: both small scans =================
__global__ void kScan() {
    int t = threadIdx.x;
    unsigned lane = t & 31, w = t >> 5;

    { // vertex block bases (1073 ints, 2/thread)
        int i0 = 2 * t, i1 = 2 * t + 1;
        int e0 = (i0 < NVB) ? g_vblk[i0] : 0;
        int e1 = (i1 < NVB) ? g_vblk[i1] : 0;
        int val = e0 + e1;
        int incl = val;
        #pragma unroll
        for (int o = 1; o < 32; o <<= 1) {
            int n = __shfl_up_sync(0xffffffffu, incl, o);
            if (lane >= o) incl += n;
        }
        __shared__ int wsA[32];
        if (lane == 31) wsA[w] = incl;
        __syncthreads();
        if (w == 0) {
            int x = wsA[lane];
            #pragma unroll
            for (int o = 1; o < 32; o <<= 1) {
                int n = __shfl_up_sync(0xffffffffu, x, o);
                if (lane >= o) x += n;
            }
            wsA[lane] = x;
        }
        __syncthreads();
        int excl = ((w > 0) ? wsA[w - 1] : 0) + incl - val;
        if (i0 < NVB) g_vblk[i0] = excl;
        if (i1 < NVB) g_vblk[i1] = excl + e0;
        if (t == 1023) { g_M = excl + val; g_vblk[NVB] = excl + val; }
        __syncthreads();
    }

    { // tet block bases (1024 u64)
        unsigned long long val = g_tblk[t];
        unsigned long long incl = val;
        #pragma unroll
        for (int o = 1; o < 32; o <<= 1) {
            unsigned long long n = __shfl_up_sync(0xffffffffu, incl, o);
            if (lane >= o) incl += n;
        }
        __shared__ unsigned long long wsB[32];
        if (lane == 31) wsB[w] = incl;
        __syncthreads();
        if (w == 0) {
            unsigned long long x = wsB[lane];
            #pragma unroll
            for (int o = 1; o < 32; o <<= 1) {
                unsigned long long n = __shfl_up_sync(0xffffffffu, x, o);
                if (lane >= o) x += n;
            }
            wsB[lane] = x;
        }
        __syncthreads();
        unsigned long long excl = ((w > 0) ? wsB[w - 1] : 0ull) + incl - val;
        g_tblk[t] = excl;
        if (t == 1023) g_F1 = (int)((excl + val) & 0xFFFFFFFFull);
    }
}

// ================= kEmit: fused verts + faces =================
__global__ void kEmit(const float* __restrict__ level, const int* __restrict__ thrp,
                      float* __restrict__ out) {
    __shared__ float    s_stage[9216];       // 36 KB: verts (<=5376) or faces (<=9216)
    __shared__ unsigned s_pack[8 * 256];     // ktB corner cache
    __shared__ int      s_tri[96];
    __shared__ int      s_edge[36];

    if (blockIdx.x < NVB) {
        // ---- emit vertices ----
        int v = blockIdx.x * 256 + threadIdx.x;
        unsigned pk = (v < NV) ? g_pkl[v] : 0u;
        unsigned mask = pk & 0x7Fu;
        int excl = (int)(pk >> 7);
        int gbase = g_vblk[blockIdx.x];
        int total = g_vblk[blockIdx.x + 1] - gbase;

        if (mask) {
            float thr = (float)thrp[0];
            const float inv = 1.0f / 64.0f;
            int i = v / ND2;
            int r = v - i * ND2;
            int j = r / NDIM;
            int k = r - j * NDIM;
            float s0  = level[v] - thr;
            float p0x = (float)i * inv, p0y = (float)j * inv, p0z = (float)k * inv;
            int sp = excl * 3;
            #pragma unroll
            for (int d = 1; d < 8; ++d) {
                if (mask & (1u << (d - 1))) {
                    int di = d >> 2, dj = (d >> 1) & 1, dk = d & 1;
                    int w = v + di * ND2 + dj * NDIM + dk;
                    float s1 = level[w] - thr;
                    float denom = s0 - s1;
                    float w0 = (-s1) / denom;
                    float w1 = s0 / denom;
                    s_stage[sp + 0] = p0x * w0 + (float)(i + di) * inv * w1;
                    s_stage[sp + 1] = p0y * w0 + (float)(j + dj) * inv * w1;
                    s_stage[sp + 2] = p0z * w0 + (float)(k + dk) * inv * w1;
                    sp += 3;
                }
            }
        }
        __syncthreads();
        float* dst = out + 3ll * gbase;
        int n = 3 * total;
        for (int x = threadIdx.x; x < n; x += 256) dst[x] = s_stage[x];
    } else {
        // ---- emit faces ----
        int tid = threadIdx.x;
        if (tid < 96) s_tri[tid] = d_tri[tid];
        if (tid < 36) {
            int ku = tid / 6, le = tid - ku * 6;
            int ba = d_kuhn[ku * 4 + d_ea[le]];
            int bb = d_kuhn[ku * 4 + d_eb[le]];
            int lo = ba & bb;
            int dd = ba ^ bb;
            int bit = (((dd & 1) << 2) | (dd & 2) | ((dd >> 2) & 1)) - 1;
            s_edge[tid] = (lo << 3) | bit;
        }

        int cb = blockIdx.x - NVB;
        int cube = cb * 256 + tid;
        int ci = cube >> 12, cj = (cube >> 6) & 63, ck = cube & 63;
        int v000 = (ci * NDIM + cj) * NDIM + ck;
        unsigned occ8 = 0;
        #pragma unroll
        for (int b = 0; b < 8; ++b)
            occ8 |= occ_bit(v000 + corner_off(b)) << b;
        int ti6[6];
        unsigned sum = cube_codes(occ8, ti6);

        // corner cache with global vertex base folded in
        #pragma unroll
        for (int c = 0; c < 8; ++c) {
            int vc = v000 + corner_off(c);
            unsigned pk = g_pkl[vc];
            s_pack[c * 256 + tid] =
                (((unsigned)g_vblk[vc >> 8] + (pk >> 7)) << 7) | (pk & 0x7Fu);
        }

        unsigned total;
        unsigned run = blockScanExcl256<unsigned>(sum, total);  // syncs cover s_* writes
        int total1 = (int)(total & 0xFFFFu);
        int total2 = (int)(total >> 16);

        // build faces into smem at block-local offsets
        #pragma unroll
        for (int ku = 0; ku < 6; ++ku) {
            int ti = ti6[ku];
            int pc = __popc(ti);
            int nt = min(pc, 4 - pc);
            if (nt == 0) continue;
            int sp;
            unsigned code;
            if (nt == 1) { sp = 3 * (int)(run & 0xFFFFu);               code = 1u; }
            else         { sp = 3 * total1 + 6 * (int)(run >> 16);      code = 0x10000u; }
            int nent = 3 * nt;
            for (int e = 0; e < nent; ++e) {
                int le = s_tri[ti * 6 + e];
                int pe = s_edge[ku * 6 + le];
                unsigned pk = s_pack[(pe >> 3) * 256 + tid];
                unsigned bit = (unsigned)(pe & 7);
                int vidx = (int)(pk >> 7) + __popc(pk & 0x7Fu & ((1u << bit) - 1u));
                s_stage[sp + e] = (float)vidx;
            }
            run += code;
        }
        __syncthreads();

        unsigned long long blk = g_tblk[cb];
        int c1base = (int)(blk & 0xFFFFFFFFull);
        int c2base = (int)(blk >> 32);
        float* fout = out + 3ll * g_M;

        float* dst1 = fout + 3ll * c1base;
        int n1 = 3 * total1;
        for (int x = tid; x < n1; x += 256) dst1[x] = s_stage[x];
        float* dst2 = fout + 3ll * (g_F1 + 2ll * c2base);
        int n2 = 6 * total2;
        const float* src2 = s_stage + n1;
        for (int x = tid; x < n2; x += 256) dst2[x] = src2[x];
    }
}

// ---------------- launch ----------------
extern "C" void kernel_launch(void* const* d_in, const int* in_sizes, int n_in,
                              void* d_out, int out_size) {
    const float* level = (const float*)d_in[0];
    const int*   thrp  = (const int*)d_in[3];
    float*       out   = (float*)d_out;
    (void)in_sizes; (void)n_in; (void)out_size;

    kCount<<<NVB + NCB, 256>>>(level, thrp);
    kScan <<<1, 1024>>>();
    kEmit <<<NVB + NCB, 256>>>(level, thrp, out);
}